// round 1
// baseline (speedup 1.0000x reference)
#include <cuda_runtime.h>
#include <math.h>

// ---------------- problem constants ----------------
#define Bv   4
#define Rv   4
#define Nv   4096
#define Mv   64
#define Kv   3
#define KNv  (Kv * Nv)        // 12288
#define BRv  (Bv * Rv)        // 16
#define P1   (BRv * KNv)      // 196608 point-copies
#define P2   (BRv * Mv)       // 1024 node-copies
#define Fv   512

// ---------------- device scratch (no dynamic alloc allowed) ----------------
__device__ float d_xdec[2 * P1];       // decentered rotated points  [2][P1]
__device__ float d_h1[64 * P1];        // fp layer activations
__device__ float d_h2[64 * P1];
__device__ float d_h3[128 * P1];
__device__ float d_feat[128 * P1];     // fp block output (relu'd, >=0)
__device__ int   d_topk[Bv * Nv * Kv]; // top-3 node index per point
__device__ float d_csum[Bv * 2 * Mv];  // cluster coordinate sums
__device__ float d_ccnt[Bv * Mv];      // cluster counts (float, matches mask_row_sum)
__device__ float d_nrot[BRv * 2 * Mv]; // rotated cluster means [br][2][M]
__device__ float d_g[130 * P2];        // gp input: rows 0-1 node_rot, 2-129 pooled
__device__ float d_A[256 * P2];
__device__ float d_B2[256 * P2];
__device__ float d_C2[512 * P2];
__device__ float d_D2[512 * P2];

// ---------------- rotation helper (match JAX: fl(2*pi)*r then /R) ----------
__device__ __forceinline__ void rot_cs(int r, float& c, float& s) {
    float th = 6.2831855f * (float)r * 0.25f;
    c = cosf(th);
    s = sinf(th);
}

// ---------------- K0: zero accumulators ----------------
__global__ void k_init() {
    int i = blockIdx.x * 256 + threadIdx.x;
    if (i < Bv * 2 * Mv) d_csum[i] = 0.f;
    if (i < Bv * Mv)     d_ccnt[i] = 0.f;
    if (i < 130 * P2)    d_g[i]    = 0.f;
}

// ---------------- K1: top-3 nearest nodes + cluster accumulation ----------
__global__ void k_topk(const float* __restrict__ x, const float* __restrict__ node) {
    int idx = blockIdx.x * 256 + threadIdx.x;   // B*N = 16384 threads
    if (idx >= Bv * Nv) return;
    int b = idx >> 12, n = idx & (Nv - 1);
    float x0 = x[b * 2 * Nv + n];
    float x1 = x[b * 2 * Nv + Nv + n];
    float d0 = 3.4e38f, d1 = 3.4e38f, d2 = 3.4e38f;
    int   i0 = 0, i1 = 0, i2 = 0;
    #pragma unroll
    for (int m = 0; m < Mv; m++) {
        float dx = x0 - __ldg(&node[b * 2 * Mv + m]);
        float dy = x1 - __ldg(&node[b * 2 * Mv + Mv + m]);
        float d = dx * dx + dy * dy;
        // strict < reproduces jax.lax.top_k stability (earlier index wins ties)
        if (d < d0)      { d2 = d1; i2 = i1; d1 = d0; i1 = i0; d0 = d; i0 = m; }
        else if (d < d1) { d2 = d1; i2 = i1; d1 = d;  i1 = m; }
        else if (d < d2) { d2 = d;  i2 = m; }
    }
    int o = idx * 3;
    d_topk[o] = i0; d_topk[o + 1] = i1; d_topk[o + 2] = i2;
    atomicAdd(&d_csum[b * 2 * Mv + i0],      x0);
    atomicAdd(&d_csum[b * 2 * Mv + Mv + i0], x1);
    atomicAdd(&d_ccnt[b * Mv + i0], 1.f);
    atomicAdd(&d_csum[b * 2 * Mv + i1],      x0);
    atomicAdd(&d_csum[b * 2 * Mv + Mv + i1], x1);
    atomicAdd(&d_ccnt[b * Mv + i1], 1.f);
    atomicAdd(&d_csum[b * 2 * Mv + i2],      x0);
    atomicAdd(&d_csum[b * 2 * Mv + Mv + i2], x1);
    atomicAdd(&d_ccnt[b * Mv + i2], 1.f);
}

// ---------------- K2: cluster means -> rotated node coords -----------------
__global__ void k_nodes() {
    int idx = threadIdx.x;                      // 256 = B*M
    int b = idx >> 6, m = idx & 63;
    float cnt = d_ccnt[b * Mv + m];
    float inv = 1.f / (cnt + 1e-5f);
    float m0 = d_csum[b * 2 * Mv + m]      * inv;
    float m1 = d_csum[b * 2 * Mv + Mv + m] * inv;
    #pragma unroll
    for (int r = 0; r < Rv; r++) {
        float c, s; rot_cs(r, c, s);
        float n0 = c * m0 - s * m1;
        float n1 = s * m0 + c * m1;
        int br = b * Rv + r;
        d_nrot[(br * 2 + 0) * Mv + m] = n0;
        d_nrot[(br * 2 + 1) * Mv + m] = n1;
        d_g[0 * P2 + br * Mv + m] = n0;   // g_in rows 0,1 = node_rot
        d_g[1 * P2 + br * Mv + m] = n1;
    }
}

// ---------------- K3: build decentered rotated point copies ----------------
__global__ void k_xdec(const float* __restrict__ x) {
    int p = blockIdx.x * 256 + threadIdx.x;     // P1 threads exactly
    int br = p / KNv; int kn = p - br * KNv;
    int b = br >> 2, r = br & 3;
    int k = kn >> 12, n = kn & (Nv - 1);
    float x0 = x[b * 2 * Nv + n];
    float x1 = x[b * 2 * Nv + Nv + n];
    float c, s; rot_cs(r, c, s);
    float xr0 = c * x0 - s * x1;
    float xr1 = s * x0 + c * x1;
    int m = d_topk[(b * Nv + n) * 3 + k];
    float cx = d_nrot[(br * 2 + 0) * Mv + m];
    float cy = d_nrot[(br * 2 + 1) * Mv + m];
    d_xdec[p]      = xr0 - cx;
    d_xdec[P1 + p] = xr1 - cy;
}

// ---------------- generic fused GEMM + bias + ReLU -------------------------
// out[o][col] = relu(bias[o] + sum_c W[o][c] * in(c)[col]),
// in(c) = in1 rows [0,C1) then in2 rows [0,C2)  (handles concat layers).
// Tile: 64 o x 64 col, 256 threads, 4x4 per thread, k-tiles of 16.
__global__ void __launch_bounds__(256) k_gemm(
    const float* __restrict__ W, const float* __restrict__ bias,
    const float* __restrict__ in1, int C1,
    const float* __restrict__ in2, int C2,
    float* __restrict__ out, int P)
{
    __shared__ __align__(16) float Wsh[16][68];   // [kk][oo], padded
    __shared__ __align__(16) float Ish[16][68];   // [kk][col], padded
    const int C = C1 + C2;
    const int col0 = blockIdx.x * 64, o0 = blockIdx.y * 64;
    const int tid = threadIdx.x, tx = tid & 15, ty = tid >> 4;
    float acc[4][4];
    #pragma unroll
    for (int i = 0; i < 4; i++)
        #pragma unroll
        for (int j = 0; j < 4; j++) acc[i][j] = 0.f;

    for (int k0 = 0; k0 < C; k0 += 16) {
        #pragma unroll
        for (int q = 0; q < 4; q++) {
            int l = tid * 4 + q; int oo = l >> 4, kk = l & 15;
            int c = k0 + kk;
            Wsh[kk][oo] = (c < C) ? W[(o0 + oo) * C + c] : 0.f;
        }
        #pragma unroll
        for (int q = 0; q < 4; q++) {
            int l = tid * 4 + q; int kk = l >> 6, cc = l & 63;
            int c = k0 + kk;
            float v = 0.f;
            if (c < C1)      v = in1[c * P + col0 + cc];
            else if (c < C)  v = in2[(c - C1) * P + col0 + cc];
            Ish[kk][cc] = v;
        }
        __syncthreads();
        #pragma unroll
        for (int kk = 0; kk < 16; kk++) {
            float4 wv = *(const float4*)&Wsh[kk][ty * 4];
            float4 iv = *(const float4*)&Ish[kk][tx * 4];
            acc[0][0] += wv.x * iv.x; acc[0][1] += wv.x * iv.y; acc[0][2] += wv.x * iv.z; acc[0][3] += wv.x * iv.w;
            acc[1][0] += wv.y * iv.x; acc[1][1] += wv.y * iv.y; acc[1][2] += wv.y * iv.z; acc[1][3] += wv.y * iv.w;
            acc[2][0] += wv.z * iv.x; acc[2][1] += wv.z * iv.y; acc[2][2] += wv.z * iv.z; acc[2][3] += wv.z * iv.w;
            acc[3][0] += wv.w * iv.x; acc[3][1] += wv.w * iv.y; acc[3][2] += wv.w * iv.z; acc[3][3] += wv.w * iv.w;
        }
        __syncthreads();
    }
    #pragma unroll
    for (int i = 0; i < 4; i++) {
        int o = o0 + ty * 4 + i;
        float bv = bias[o];
        #pragma unroll
        for (int j = 0; j < 4; j++) {
            float v = acc[i][j] + bv;
            out[o * P + col0 + tx * 4 + j] = v > 0.f ? v : 0.f;
        }
    }
}

// ---------------- K4: scatter-max per cluster (values >= 0) ----------------
__global__ void k_segmax() {
    int c = blockIdx.y;                         // 0..127 channel
    int p = blockIdx.x * 256 + threadIdx.x;     // 0..P1-1
    float v = d_feat[c * P1 + p];
    int br = p / KNv; int kn = p - br * KNv;
    int b = br >> 2; int k = kn >> 12, n = kn & (Nv - 1);
    int m = d_topk[(b * Nv + n) * 3 + k];
    // nonneg floats: uint bit-pattern order == float order
    atomicMax((unsigned int*)&d_g[(2 + c) * P2 + br * Mv + m], __float_as_uint(v));
}

// ---------------- K5: empty-cluster fallback = feat[:, :, 0] ---------------
__global__ void k_fix() {
    int idx = blockIdx.x * 256 + threadIdx.x;   // 16*128*64 = 131072
    int m = idx & 63; int c = (idx >> 6) & 127; int br = idx >> 13;
    int b = br >> 2;
    if (d_ccnt[b * Mv + m] == 0.f)
        d_g[(2 + c) * P2 + br * Mv + m] = d_feat[c * P1 + br * KNv];
}

// ---------------- K6: final max over (r, m) ---------------------------------
__global__ void k_reduce(float* __restrict__ out) {
    int idx = blockIdx.x * 256 + threadIdx.x;   // 2048 = B*F
    int b = idx >> 9, f = idx & 511;
    const float* src = &d_D2[f * P2 + b * 256]; // 256 contiguous (r,m) cols per b
    float v = 0.f;                              // relu outputs are >= 0
    #pragma unroll 8
    for (int j = 0; j < 256; j++) v = fmaxf(v, src[j]);
    out[b * Fv + f] = v;
}

// ---------------- host launcher ---------------------------------------------
extern "C" void kernel_launch(void* const* d_in, const int* in_sizes, int n_in,
                              void* d_out, int out_size) {
    const float* x    = (const float*)d_in[0];
    // d_in[1] intensity, d_in[3] node_knn_I: unused by reference
    const float* node = (const float*)d_in[2];
    const float* fpW0 = (const float*)d_in[4];  const float* fpb0 = (const float*)d_in[5];
    const float* fpW1 = (const float*)d_in[6];  const float* fpb1 = (const float*)d_in[7];
    const float* fpW2 = (const float*)d_in[8];  const float* fpb2 = (const float*)d_in[9];
    const float* fpW3 = (const float*)d_in[10]; const float* fpb3 = (const float*)d_in[11];
    const float* gpW0 = (const float*)d_in[12]; const float* gpb0 = (const float*)d_in[13];
    const float* gpW1 = (const float*)d_in[14]; const float* gpb1 = (const float*)d_in[15];
    const float* gpW2 = (const float*)d_in[16]; const float* gpb2 = (const float*)d_in[17];
    const float* gpW3 = (const float*)d_in[18]; const float* gpb3 = (const float*)d_in[19];

    float *p_xdec, *p_h1, *p_h2, *p_h3, *p_feat, *p_g, *p_A, *p_B2, *p_C2, *p_D2;
    cudaGetSymbolAddress((void**)&p_xdec, d_xdec);
    cudaGetSymbolAddress((void**)&p_h1,   d_h1);
    cudaGetSymbolAddress((void**)&p_h2,   d_h2);
    cudaGetSymbolAddress((void**)&p_h3,   d_h3);
    cudaGetSymbolAddress((void**)&p_feat, d_feat);
    cudaGetSymbolAddress((void**)&p_g,    d_g);
    cudaGetSymbolAddress((void**)&p_A,    d_A);
    cudaGetSymbolAddress((void**)&p_B2,   d_B2);
    cudaGetSymbolAddress((void**)&p_C2,   d_C2);
    cudaGetSymbolAddress((void**)&p_D2,   d_D2);

    k_init<<<(130 * P2 + 255) / 256, 256>>>();
    k_topk<<<(Bv * Nv) / 256, 256>>>(x, node);
    k_nodes<<<1, 256>>>();
    k_xdec<<<P1 / 256, 256>>>(x);

    // fp block (per-point MLP), 196608 columns
    k_gemm<<<dim3(P1 / 64, 1), 256>>>(fpW0, fpb0, p_xdec, 2,  nullptr, 0,   p_h1,   P1);
    k_gemm<<<dim3(P1 / 64, 1), 256>>>(fpW1, fpb1, p_h1,  64,  nullptr, 0,   p_h2,   P1);
    k_gemm<<<dim3(P1 / 64, 2), 256>>>(fpW2, fpb2, p_h2,  64,  nullptr, 0,   p_h3,   P1);
    k_gemm<<<dim3(P1 / 64, 2), 256>>>(fpW3, fpb3, p_xdec, 2,  p_h3,  128,   p_feat, P1);

    k_segmax<<<dim3(P1 / 256, 128), 256>>>();
    k_fix<<<(BRv * 128 * Mv) / 256, 256>>>();

    // gp block (per-node MLP), 1024 columns
    k_gemm<<<dim3(P2 / 64, 4), 256>>>(gpW0, gpb0, p_g,  130,  nullptr, 0,   p_A,  P2);
    k_gemm<<<dim3(P2 / 64, 4), 256>>>(gpW1, gpb1, p_A,  256,  nullptr, 0,   p_B2, P2);
    k_gemm<<<dim3(P2 / 64, 8), 256>>>(gpW2, gpb2, p_B2, 256,  nullptr, 0,   p_C2, P2);
    k_gemm<<<dim3(P2 / 64, 8), 256>>>(gpW3, gpb3, p_g,  130,  p_C2,  512,   p_D2, P2);

    k_reduce<<<(Bv * Fv) / 256, 256>>>((float*)d_out);
}

// round 2
// speedup vs baseline: 1.4319x; 1.4319x over previous
#include <cuda_runtime.h>
#include <math.h>

// ---------------- problem constants ----------------
#define Bv   4
#define Rv   4
#define Nv   4096
#define Mv   64
#define KNv  12288            // K*N
#define BRv  16               // B*R
#define P1   196608           // BR*KN point-copies
#define P2   1024             // BR*M node-copies
#define Fv   512
#define TILES 3072            // P1 / 64
#define TPB   192             // tiles per br (KN/64)

// ---------------- device scratch ----------------
__device__ int   d_topk[Bv * Nv * 3];
__device__ float d_csum[Bv * 2 * Mv];
__device__ float d_ccnt[Bv * Mv];
__device__ float d_nrot[BRv * 2 * Mv];
__device__ float d_g[130 * P2];        // rows 0-1 node_rot, 2-129 pooled (REDG.MAX targets)
__device__ float d_fcol0[BRv * 128];   // feat[:, :, 0] per br (empty-cluster fallback)
__device__ float d_A[256 * P2];
__device__ float d_B2[256 * P2];
__device__ float d_C2[512 * P2];
__device__ float d_D2[512 * P2];

// ---------------- packed f32x2 helpers ----------------
__device__ __forceinline__ unsigned long long ffma2(unsigned long long a,
                                                    unsigned long long b,
                                                    unsigned long long c) {
    unsigned long long d;
    asm("fma.rn.f32x2 %0, %1, %2, %3;" : "=l"(d) : "l"(a), "l"(b), "l"(c));
    return d;
}
__device__ __forceinline__ float lo2(unsigned long long a) { return __uint_as_float((unsigned)a); }
__device__ __forceinline__ float hi2(unsigned long long a) { return __uint_as_float((unsigned)(a >> 32)); }

__device__ __forceinline__ void rot_cs(int r, float& c, float& s) {
    float th = 6.2831855f * (float)r * 0.25f;
    c = cosf(th);
    s = sinf(th);
}

// ---------------- K0: zero accumulators ----------------
__global__ void k_init() {
    int i = blockIdx.x * 256 + threadIdx.x;
    if (i < Bv * 2 * Mv) d_csum[i] = 0.f;
    if (i < Bv * Mv)     d_ccnt[i] = 0.f;
    if (i < 130 * P2)    d_g[i]    = 0.f;
}

// ---------------- K1: top-3 nearest nodes + cluster accumulation ----------
__global__ void k_topk(const float* __restrict__ x, const float* __restrict__ node) {
    int idx = blockIdx.x * 256 + threadIdx.x;
    if (idx >= Bv * Nv) return;
    int b = idx >> 12, n = idx & (Nv - 1);
    float x0 = x[b * 2 * Nv + n];
    float x1 = x[b * 2 * Nv + Nv + n];
    float d0 = 3.4e38f, d1 = 3.4e38f, d2 = 3.4e38f;
    int   i0 = 0, i1 = 0, i2 = 0;
    #pragma unroll
    for (int m = 0; m < Mv; m++) {
        float dx = x0 - __ldg(&node[b * 2 * Mv + m]);
        float dy = x1 - __ldg(&node[b * 2 * Mv + Mv + m]);
        float d = dx * dx + dy * dy;
        if (d < d0)      { d2 = d1; i2 = i1; d1 = d0; i1 = i0; d0 = d; i0 = m; }
        else if (d < d1) { d2 = d1; i2 = i1; d1 = d;  i1 = m; }
        else if (d < d2) { d2 = d;  i2 = m; }
    }
    int o = idx * 3;
    d_topk[o] = i0; d_topk[o + 1] = i1; d_topk[o + 2] = i2;
    atomicAdd(&d_csum[b * 2 * Mv + i0],      x0);
    atomicAdd(&d_csum[b * 2 * Mv + Mv + i0], x1);
    atomicAdd(&d_ccnt[b * Mv + i0], 1.f);
    atomicAdd(&d_csum[b * 2 * Mv + i1],      x0);
    atomicAdd(&d_csum[b * 2 * Mv + Mv + i1], x1);
    atomicAdd(&d_ccnt[b * Mv + i1], 1.f);
    atomicAdd(&d_csum[b * 2 * Mv + i2],      x0);
    atomicAdd(&d_csum[b * 2 * Mv + Mv + i2], x1);
    atomicAdd(&d_ccnt[b * Mv + i2], 1.f);
}

// ---------------- K2: cluster means -> rotated node coords -----------------
__global__ void k_nodes() {
    int idx = threadIdx.x;                      // 256 = B*M
    int b = idx >> 6, m = idx & 63;
    float cnt = d_ccnt[b * Mv + m];
    float inv = 1.f / (cnt + 1e-5f);
    float m0 = d_csum[b * 2 * Mv + m]      * inv;
    float m1 = d_csum[b * 2 * Mv + Mv + m] * inv;
    #pragma unroll
    for (int r = 0; r < Rv; r++) {
        float c, s; rot_cs(r, c, s);
        float n0 = c * m0 - s * m1;
        float n1 = s * m0 + c * m1;
        int br = b * Rv + r;
        d_nrot[(br * 2 + 0) * Mv + m] = n0;
        d_nrot[(br * 2 + 1) * Mv + m] = n1;
        d_g[0 * P2 + br * Mv + m] = n0;
        d_g[1 * P2 + br * Mv + m] = n1;
    }
}

// ---------------- fused fp block: xdec -> 4-layer MLP -> scatter-max -------
// smem layout (float offsets)
#define SW0  0
#define SB0  128
#define SB1  192
#define SB2  256
#define SB3  384
#define SW1  512        // [k][64]
#define SW2  4608       // [k][128]
#define SW3  12800      // [k][128], 132 rows
#define SXS  29696      // float2[2][64] dup
#define SMS  29952      // int[64]
#define SBA  30016      // float2[64][64]
#define SBB  38208      // float2[64][64]
#define SBC  46400      // float2[64][64]
#define SMEM_FLOATS 54592

__global__ void __launch_bounds__(256, 1) k_fp(
    const float* __restrict__ x,
    const float* __restrict__ W0, const float* __restrict__ b0,
    const float* __restrict__ W1, const float* __restrict__ b1,
    const float* __restrict__ W2, const float* __restrict__ b2,
    const float* __restrict__ W3, const float* __restrict__ b3)
{
    extern __shared__ float sm[];
    const int tid = threadIdx.x;

    // ---- stage weights (transposed to [k][o]) ----
    for (int i = tid; i < 128; i += 256) sm[SW0 + i] = W0[i];
    for (int i = tid; i < 64;  i += 256) { sm[SB0 + i] = b0[i]; sm[SB1 + i] = b1[i]; }
    for (int i = tid; i < 128; i += 256) { sm[SB2 + i] = b2[i]; sm[SB3 + i] = b3[i]; }
    for (int i = tid; i < 4096; i += 256) { int o = i & 63,  k = i >> 6; sm[SW1 + k * 64  + o] = W1[o * 64  + k]; }
    for (int i = tid; i < 8192; i += 256) { int o = i & 127, k = i >> 7; sm[SW2 + k * 128 + o] = W2[o * 64  + k]; }
    for (int i = tid; i < 130 * 128; i += 256) { int o = i & 127, k = i >> 7; sm[SW3 + k * 128 + o] = W3[o * 130 + k]; }
    __syncthreads();

    float2* xs2 = (float2*)(sm + SXS);
    int*    ms  = (int*)(sm + SMS);
    float2* bA  = (float2*)(sm + SBA);
    float2* bB  = (float2*)(sm + SBB);
    float2* bC  = (float2*)(sm + SBC);

    for (int t = blockIdx.x; t < TILES; t += gridDim.x) {
        int br = t / TPB; int tloc = t - br * TPB; int kn0 = tloc * 64;
        int b = br >> 2, r = br & 3;

        // ---- P0: xdec prologue ----
        if (tid < 64) {
            int kn = kn0 + tid; int k = kn >> 12; int n = kn & (Nv - 1);
            float x0 = x[b * 2 * Nv + n], x1 = x[b * 2 * Nv + Nv + n];
            float c, s; rot_cs(r, c, s);
            float xr0 = c * x0 - s * x1;
            float xr1 = s * x0 + c * x1;
            int m = d_topk[(b * Nv + n) * 3 + k];
            float v0 = xr0 - d_nrot[(br * 2 + 0) * Mv + m];
            float v1 = xr1 - d_nrot[(br * 2 + 1) * Mv + m];
            xs2[tid]      = make_float2(v0, v0);
            xs2[64 + tid] = make_float2(v1, v1);
            ms[tid] = m;
        }
        __syncthreads();

        // ---- L0: 64 x 64, K=2 ----
        {
            int o0 = (tid >> 4) * 4, p0 = (tid & 15) * 4;
            #pragma unroll
            for (int i = 0; i < 4; i++) {
                int o = o0 + i;
                float w0 = sm[SW0 + o * 2], w1 = sm[SW0 + o * 2 + 1], bb = sm[SB0 + o];
                #pragma unroll
                for (int j = 0; j < 4; j++) {
                    int p = p0 + j;
                    float v = fmaf(w0, xs2[p].x, fmaf(w1, xs2[64 + p].x, bb));
                    v = fmaxf(v, 0.f);
                    bA[o * 64 + p] = make_float2(v, v);
                }
            }
        }
        __syncthreads();

        // ---- L1: 64 x 64, K=64 (bufA -> bufB) ----
        {
            int o0 = (tid >> 5) * 8, p0 = (tid & 31) * 2;
            unsigned long long acc[4][2];
            #pragma unroll
            for (int i = 0; i < 4; i++) { acc[i][0] = 0ull; acc[i][1] = 0ull; }
            #pragma unroll 8
            for (int kk = 0; kk < 64; kk++) {
                ulonglong2 wA = *(const ulonglong2*)&sm[SW1 + kk * 64 + o0];
                ulonglong2 wB = *(const ulonglong2*)&sm[SW1 + kk * 64 + o0 + 4];
                ulonglong2 iv = *(const ulonglong2*)&bA[kk * 64 + p0];
                acc[0][0] = ffma2(wA.x, iv.x, acc[0][0]); acc[0][1] = ffma2(wA.x, iv.y, acc[0][1]);
                acc[1][0] = ffma2(wA.y, iv.x, acc[1][0]); acc[1][1] = ffma2(wA.y, iv.y, acc[1][1]);
                acc[2][0] = ffma2(wB.x, iv.x, acc[2][0]); acc[2][1] = ffma2(wB.x, iv.y, acc[2][1]);
                acc[3][0] = ffma2(wB.y, iv.x, acc[3][0]); acc[3][1] = ffma2(wB.y, iv.y, acc[3][1]);
            }
            #pragma unroll
            for (int i = 0; i < 4; i++) {
                int o = o0 + 2 * i;
                float bl = sm[SB1 + o], bh = sm[SB1 + o + 1];
                #pragma unroll
                for (int j = 0; j < 2; j++) {
                    float vl = fmaxf(lo2(acc[i][j]) + bl, 0.f);
                    float vh = fmaxf(hi2(acc[i][j]) + bh, 0.f);
                    bB[o * 64 + p0 + j]       = make_float2(vl, vl);
                    bB[(o + 1) * 64 + p0 + j] = make_float2(vh, vh);
                }
            }
        }
        __syncthreads();

        // ---- L2: 128 x 64, K=64 (bufB -> bufA rows 0-63 / bufC rows 64-127) ----
        {
            int o0 = (tid >> 4) * 8, p0 = (tid & 15) * 4;
            unsigned long long acc[4][4];
            #pragma unroll
            for (int i = 0; i < 4; i++)
                #pragma unroll
                for (int j = 0; j < 4; j++) acc[i][j] = 0ull;
            #pragma unroll 4
            for (int kk = 0; kk < 64; kk++) {
                ulonglong2 wA  = *(const ulonglong2*)&sm[SW2 + kk * 128 + o0];
                ulonglong2 wB  = *(const ulonglong2*)&sm[SW2 + kk * 128 + o0 + 4];
                ulonglong2 ivA = *(const ulonglong2*)&bB[kk * 64 + p0];
                ulonglong2 ivB = *(const ulonglong2*)&bB[kk * 64 + p0 + 2];
                acc[0][0] = ffma2(wA.x, ivA.x, acc[0][0]); acc[0][1] = ffma2(wA.x, ivA.y, acc[0][1]);
                acc[0][2] = ffma2(wA.x, ivB.x, acc[0][2]); acc[0][3] = ffma2(wA.x, ivB.y, acc[0][3]);
                acc[1][0] = ffma2(wA.y, ivA.x, acc[1][0]); acc[1][1] = ffma2(wA.y, ivA.y, acc[1][1]);
                acc[1][2] = ffma2(wA.y, ivB.x, acc[1][2]); acc[1][3] = ffma2(wA.y, ivB.y, acc[1][3]);
                acc[2][0] = ffma2(wB.x, ivA.x, acc[2][0]); acc[2][1] = ffma2(wB.x, ivA.y, acc[2][1]);
                acc[2][2] = ffma2(wB.x, ivB.x, acc[2][2]); acc[2][3] = ffma2(wB.x, ivB.y, acc[2][3]);
                acc[3][0] = ffma2(wB.y, ivA.x, acc[3][0]); acc[3][1] = ffma2(wB.y, ivA.y, acc[3][1]);
                acc[3][2] = ffma2(wB.y, ivB.x, acc[3][2]); acc[3][3] = ffma2(wB.y, ivB.y, acc[3][3]);
            }
            float2* dst = (o0 < 64) ? (bA + o0 * 64) : (bC + (o0 - 64) * 64);
            #pragma unroll
            for (int i = 0; i < 4; i++) {
                int o = o0 + 2 * i;
                float bl = sm[SB2 + o], bh = sm[SB2 + o + 1];
                #pragma unroll
                for (int j = 0; j < 4; j++) {
                    float vl = fmaxf(lo2(acc[i][j]) + bl, 0.f);
                    float vh = fmaxf(hi2(acc[i][j]) + bh, 0.f);
                    dst[(2 * i) * 64 + p0 + j]     = make_float2(vl, vl);
                    dst[(2 * i + 1) * 64 + p0 + j] = make_float2(vh, vh);
                }
            }
        }
        __syncthreads();

        // ---- L3: 128 x 64, K=130 = concat(x(2), h3(128)) -> REDG epilogue ----
        {
            int o0 = (tid >> 4) * 8, p0 = (tid & 15) * 4;
            unsigned long long acc[4][4];
            #pragma unroll
            for (int i = 0; i < 4; i++)
                #pragma unroll
                for (int j = 0; j < 4; j++) acc[i][j] = 0ull;
            #pragma unroll
            for (int k = 0; k < 2; k++) {
                ulonglong2 wA  = *(const ulonglong2*)&sm[SW3 + k * 128 + o0];
                ulonglong2 wB  = *(const ulonglong2*)&sm[SW3 + k * 128 + o0 + 4];
                ulonglong2 ivA = *(const ulonglong2*)&xs2[k * 64 + p0];
                ulonglong2 ivB = *(const ulonglong2*)&xs2[k * 64 + p0 + 2];
                acc[0][0] = ffma2(wA.x, ivA.x, acc[0][0]); acc[0][1] = ffma2(wA.x, ivA.y, acc[0][1]);
                acc[0][2] = ffma2(wA.x, ivB.x, acc[0][2]); acc[0][3] = ffma2(wA.x, ivB.y, acc[0][3]);
                acc[1][0] = ffma2(wA.y, ivA.x, acc[1][0]); acc[1][1] = ffma2(wA.y, ivA.y, acc[1][1]);
                acc[1][2] = ffma2(wA.y, ivB.x, acc[1][2]); acc[1][3] = ffma2(wA.y, ivB.y, acc[1][3]);
                acc[2][0] = ffma2(wB.x, ivA.x, acc[2][0]); acc[2][1] = ffma2(wB.x, ivA.y, acc[2][1]);
                acc[2][2] = ffma2(wB.x, ivB.x, acc[2][2]); acc[2][3] = ffma2(wB.x, ivB.y, acc[2][3]);
                acc[3][0] = ffma2(wB.y, ivA.x, acc[3][0]); acc[3][1] = ffma2(wB.y, ivA.y, acc[3][1]);
                acc[3][2] = ffma2(wB.y, ivB.x, acc[3][2]); acc[3][3] = ffma2(wB.y, ivB.y, acc[3][3]);
            }
            #pragma unroll 4
            for (int kk = 0; kk < 64; kk++) {                    // h3 rows 0-63 in bufA
                ulonglong2 wA  = *(const ulonglong2*)&sm[SW3 + (2 + kk) * 128 + o0];
                ulonglong2 wB  = *(const ulonglong2*)&sm[SW3 + (2 + kk) * 128 + o0 + 4];
                ulonglong2 ivA = *(const ulonglong2*)&bA[kk * 64 + p0];
                ulonglong2 ivB = *(const ulonglong2*)&bA[kk * 64 + p0 + 2];
                acc[0][0] = ffma2(wA.x, ivA.x, acc[0][0]); acc[0][1] = ffma2(wA.x, ivA.y, acc[0][1]);
                acc[0][2] = ffma2(wA.x, ivB.x, acc[0][2]); acc[0][3] = ffma2(wA.x, ivB.y, acc[0][3]);
                acc[1][0] = ffma2(wA.y, ivA.x, acc[1][0]); acc[1][1] = ffma2(wA.y, ivA.y, acc[1][1]);
                acc[1][2] = ffma2(wA.y, ivB.x, acc[1][2]); acc[1][3] = ffma2(wA.y, ivB.y, acc[1][3]);
                acc[2][0] = ffma2(wB.x, ivA.x, acc[2][0]); acc[2][1] = ffma2(wB.x, ivA.y, acc[2][1]);
                acc[2][2] = ffma2(wB.x, ivB.x, acc[2][2]); acc[2][3] = ffma2(wB.x, ivB.y, acc[2][3]);
                acc[3][0] = ffma2(wB.y, ivA.x, acc[3][0]); acc[3][1] = ffma2(wB.y, ivA.y, acc[3][1]);
                acc[3][2] = ffma2(wB.y, ivB.x, acc[3][2]); acc[3][3] = ffma2(wB.y, ivB.y, acc[3][3]);
            }
            #pragma unroll 4
            for (int kk = 0; kk < 64; kk++) {                    // h3 rows 64-127 in bufC
                ulonglong2 wA  = *(const ulonglong2*)&sm[SW3 + (66 + kk) * 128 + o0];
                ulonglong2 wB  = *(const ulonglong2*)&sm[SW3 + (66 + kk) * 128 + o0 + 4];
                ulonglong2 ivA = *(const ulonglong2*)&bC[kk * 64 + p0];
                ulonglong2 ivB = *(const ulonglong2*)&bC[kk * 64 + p0 + 2];
                acc[0][0] = ffma2(wA.x, ivA.x, acc[0][0]); acc[0][1] = ffma2(wA.x, ivA.y, acc[0][1]);
                acc[0][2] = ffma2(wA.x, ivB.x, acc[0][2]); acc[0][3] = ffma2(wA.x, ivB.y, acc[0][3]);
                acc[1][0] = ffma2(wA.y, ivA.x, acc[1][0]); acc[1][1] = ffma2(wA.y, ivA.y, acc[1][1]);
                acc[1][2] = ffma2(wA.y, ivB.x, acc[1][2]); acc[1][3] = ffma2(wA.y, ivB.y, acc[1][3]);
                acc[2][0] = ffma2(wB.x, ivA.x, acc[2][0]); acc[2][1] = ffma2(wB.x, ivA.y, acc[2][1]);
                acc[2][2] = ffma2(wB.x, ivB.x, acc[2][2]); acc[2][3] = ffma2(wB.x, ivB.y, acc[2][3]);
                acc[3][0] = ffma2(wB.y, ivA.x, acc[3][0]); acc[3][1] = ffma2(wB.y, ivA.y, acc[3][1]);
                acc[3][2] = ffma2(wB.y, ivB.x, acc[3][2]); acc[3][3] = ffma2(wB.y, ivB.y, acc[3][3]);
            }
            // epilogue: bias + relu + scatter-max (nonneg float == uint order)
            int mj[4] = { ms[p0], ms[p0 + 1], ms[p0 + 2], ms[p0 + 3] };
            int tx0 = ((tid & 15) == 0);
            #pragma unroll
            for (int i = 0; i < 4; i++) {
                int o = o0 + 2 * i;
                float bl = sm[SB3 + o], bh = sm[SB3 + o + 1];
                #pragma unroll
                for (int j = 0; j < 4; j++) {
                    float vl = fmaxf(lo2(acc[i][j]) + bl, 0.f);
                    float vh = fmaxf(hi2(acc[i][j]) + bh, 0.f);
                    int base = br * Mv + mj[j];
                    atomicMax((unsigned*)&d_g[(2 + o) * P2 + base], __float_as_uint(vl));
                    atomicMax((unsigned*)&d_g[(3 + o) * P2 + base], __float_as_uint(vh));
                    if (tloc == 0 && tx0 && j == 0) {
                        d_fcol0[br * 128 + o]     = vl;
                        d_fcol0[br * 128 + o + 1] = vh;
                    }
                }
            }
        }
        __syncthreads();
    }
}

// ---------------- K5: empty-cluster fallback = feat[:, :, 0] ---------------
__global__ void k_fix() {
    int idx = blockIdx.x * 256 + threadIdx.x;   // 16*128*64 = 131072
    int m = idx & 63; int c = (idx >> 6) & 127; int br = idx >> 13;
    int b = br >> 2;
    if (d_ccnt[b * Mv + m] == 0.f)
        d_g[(2 + c) * P2 + br * Mv + m] = d_fcol0[br * 128 + c];
}

// ---------------- generic fused GEMM + bias + ReLU (gp block) --------------
__global__ void __launch_bounds__(256) k_gemm(
    const float* __restrict__ W, const float* __restrict__ bias,
    const float* __restrict__ in1, int C1,
    const float* __restrict__ in2, int C2,
    float* __restrict__ out, int P)
{
    __shared__ __align__(16) float Wsh[16][68];
    __shared__ __align__(16) float Ish[16][68];
    const int C = C1 + C2;
    const int col0 = blockIdx.x * 64, o0 = blockIdx.y * 64;
    const int tid = threadIdx.x, tx = tid & 15, ty = tid >> 4;
    float acc[4][4];
    #pragma unroll
    for (int i = 0; i < 4; i++)
        #pragma unroll
        for (int j = 0; j < 4; j++) acc[i][j] = 0.f;

    for (int k0 = 0; k0 < C; k0 += 16) {
        #pragma unroll
        for (int q = 0; q < 4; q++) {
            int l = tid * 4 + q; int oo = l >> 4, kk = l & 15;
            int c = k0 + kk;
            Wsh[kk][oo] = (c < C) ? W[(o0 + oo) * C + c] : 0.f;
        }
        #pragma unroll
        for (int q = 0; q < 4; q++) {
            int l = tid * 4 + q; int kk = l >> 6, cc = l & 63;
            int c = k0 + kk;
            float v = 0.f;
            if (c < C1)      v = in1[c * P + col0 + cc];
            else if (c < C)  v = in2[(c - C1) * P + col0 + cc];
            Ish[kk][cc] = v;
        }
        __syncthreads();
        #pragma unroll
        for (int kk = 0; kk < 16; kk++) {
            float4 wv = *(const float4*)&Wsh[kk][ty * 4];
            float4 iv = *(const float4*)&Ish[kk][tx * 4];
            acc[0][0] += wv.x * iv.x; acc[0][1] += wv.x * iv.y; acc[0][2] += wv.x * iv.z; acc[0][3] += wv.x * iv.w;
            acc[1][0] += wv.y * iv.x; acc[1][1] += wv.y * iv.y; acc[1][2] += wv.y * iv.z; acc[1][3] += wv.y * iv.w;
            acc[2][0] += wv.z * iv.x; acc[2][1] += wv.z * iv.y; acc[2][2] += wv.z * iv.z; acc[2][3] += wv.z * iv.w;
            acc[3][0] += wv.w * iv.x; acc[3][1] += wv.w * iv.y; acc[3][2] += wv.w * iv.z; acc[3][3] += wv.w * iv.w;
        }
        __syncthreads();
    }
    #pragma unroll
    for (int i = 0; i < 4; i++) {
        int o = o0 + ty * 4 + i;
        float bv = bias[o];
        #pragma unroll
        for (int j = 0; j < 4; j++) {
            float v = acc[i][j] + bv;
            out[o * P + col0 + tx * 4 + j] = v > 0.f ? v : 0.f;
        }
    }
}

// ---------------- K6: final max over (r, m) ---------------------------------
__global__ void k_reduce(float* __restrict__ out) {
    int idx = blockIdx.x * 256 + threadIdx.x;   // 2048 = B*F
    int b = idx >> 9, f = idx & 511;
    const float* src = &d_D2[f * P2 + b * 256];
    float v = 0.f;
    #pragma unroll 8
    for (int j = 0; j < 256; j++) v = fmaxf(v, src[j]);
    out[b * Fv + f] = v;
}

// ---------------- host launcher ---------------------------------------------
extern "C" void kernel_launch(void* const* d_in, const int* in_sizes, int n_in,
                              void* d_out, int out_size) {
    const float* x    = (const float*)d_in[0];
    const float* node = (const float*)d_in[2];
    const float* fpW0 = (const float*)d_in[4];  const float* fpb0 = (const float*)d_in[5];
    const float* fpW1 = (const float*)d_in[6];  const float* fpb1 = (const float*)d_in[7];
    const float* fpW2 = (const float*)d_in[8];  const float* fpb2 = (const float*)d_in[9];
    const float* fpW3 = (const float*)d_in[10]; const float* fpb3 = (const float*)d_in[11];
    const float* gpW0 = (const float*)d_in[12]; const float* gpb0 = (const float*)d_in[13];
    const float* gpW1 = (const float*)d_in[14]; const float* gpb1 = (const float*)d_in[15];
    const float* gpW2 = (const float*)d_in[16]; const float* gpb2 = (const float*)d_in[17];
    const float* gpW3 = (const float*)d_in[18]; const float* gpb3 = (const float*)d_in[19];

    float *p_g, *p_A, *p_B2, *p_C2, *p_D2;
    cudaGetSymbolAddress((void**)&p_g,  d_g);
    cudaGetSymbolAddress((void**)&p_A,  d_A);
    cudaGetSymbolAddress((void**)&p_B2, d_B2);
    cudaGetSymbolAddress((void**)&p_C2, d_C2);
    cudaGetSymbolAddress((void**)&p_D2, d_D2);

    static int smem_set = 0;
    if (!smem_set) {
        cudaFuncSetAttribute(k_fp, cudaFuncAttributeMaxDynamicSharedMemorySize,
                             SMEM_FLOATS * 4);
        smem_set = 1;
    }

    k_init<<<(130 * P2 + 255) / 256, 256>>>();
    k_topk<<<(Bv * Nv) / 256, 256>>>(x, node);
    k_nodes<<<1, 256>>>();

    k_fp<<<304, 256, SMEM_FLOATS * 4>>>(x, fpW0, fpb0, fpW1, fpb1,
                                        fpW2, fpb2, fpW3, fpb3);
    k_fix<<<(BRv * 128 * Mv) / 256, 256>>>();

    // gp block (per-node MLP), 1024 columns
    k_gemm<<<dim3(P2 / 64, 4), 256>>>(gpW0, gpb0, p_g,  130, nullptr, 0,   p_A,  P2);
    k_gemm<<<dim3(P2 / 64, 4), 256>>>(gpW1, gpb1, p_A,  256, nullptr, 0,   p_B2, P2);
    k_gemm<<<dim3(P2 / 64, 8), 256>>>(gpW2, gpb2, p_B2, 256, nullptr, 0,   p_C2, P2);
    k_gemm<<<dim3(P2 / 64, 8), 256>>>(gpW3, gpb3, p_g,  130, p_C2,  512,   p_D2, P2);

    k_reduce<<<(Bv * Fv) / 256, 256>>>((float*)d_out);
}